// round 12
// baseline (speedup 1.0000x reference)
#include <cuda_runtime.h>

typedef unsigned long long u64;

#define NK 16
#define TW 136           // tile row stride in floats (col c stores gcol = bx*128 + c - 4)

struct CB {
    u64 crec[NK][16];    // [u[i][j] i=0..3,j=0..2 (dup), mk(dup), pk(dup), pad, pad]
};

__device__   CB g_cb;
__constant__ CB c_cb;

__device__ __forceinline__ u64 pack2(float lo, float hi) {
    u64 r; asm("mov.b64 %0, {%1, %2};" : "=l"(r) : "f"(lo), "f"(hi)); return r;
}
__device__ __forceinline__ void unpack2(u64 v, float& lo, float& hi) {
    asm("mov.b64 {%0, %1}, %2;" : "=f"(lo), "=f"(hi) : "l"(v));
}
__device__ __forceinline__ u64 fma2(u64 a, u64 b, u64 c) {
    u64 d; asm("fma.rn.f32x2 %0, %1, %2, %3;" : "=l"(d) : "l"(a), "l"(b), "l"(c)); return d;
}
__device__ __forceinline__ u64 mul2_(u64 a, u64 b) {
    u64 d; asm("mul.rn.f32x2 %0, %1, %2;" : "=l"(d) : "l"(a), "l"(b)); return d;
}
__device__ __forceinline__ u64 add2_(u64 a, u64 b) {
    u64 d; asm("add.rn.f32x2 %0, %1, %2;" : "=l"(d) : "l"(a), "l"(b)); return d;
}
__device__ __forceinline__ u64 sub2_(u64 a, u64 b) {
    u64 d; asm("sub.rn.f32x2 %0, %1, %2;" : "=l"(d) : "l"(a), "l"(b)); return d;
}
__device__ __forceinline__ float sat_(float a) {
    float r; asm("add.rn.sat.f32 %0, %1, 0f00000000;" : "=f"(r) : "f"(a)); return r;
}

// Complete paired-sigmoid tail for one column: sigmaA = 1/(1+2^wA),
// sigmaB = 1/(1+2^wB) via ONE shared rcp per half; accumulators updated
// in place. Every instruction hand-authored -- no compiler-inserted MOVs.
__device__ __forceinline__ void pair_sig_acc(u64 zA, u64 zB, u64 pA2, u64 pB2,
                                             u64& aP, u64& aS) {
    asm("{\n\t"
        ".reg .f32 a,b,c,d,e,f,g,h,i,j;\n\t"
        ".reg .b64 s1,s2;\n\t"
        "mov.b64 {a,b}, %2;\n\t"
        "mov.b64 {c,d}, %3;\n\t"
        "min.f32 a, a, 0f42700000;\n\t"    // clamp w <= 60
        "min.f32 b, b, 0f42700000;\n\t"
        "min.f32 c, c, 0f42700000;\n\t"
        "min.f32 d, d, 0f42700000;\n\t"
        "ex2.approx.f32 a, a;\n\t"         // tA halves
        "ex2.approx.f32 b, b;\n\t"
        "ex2.approx.f32 c, c;\n\t"         // tB halves
        "ex2.approx.f32 d, d;\n\t"
        "add.f32 a, a, 0f3F800000;\n\t"    // uA = 1 + tA
        "add.f32 b, b, 0f3F800000;\n\t"
        "add.f32 c, c, 0f3F800000;\n\t"    // uB = 1 + tB
        "add.f32 d, d, 0f3F800000;\n\t"
        "mul.f32 e, a, c;\n\t"             // den half0
        "mul.f32 f, b, d;\n\t"             // den half1
        "rcp.approx.f32 e, e;\n\t"         // one rcp serves both kernels
        "rcp.approx.f32 f, f;\n\t"
        "mul.f32 g, e, c;\n\t"             // sigmaA half0 = uB0/den0
        "mul.f32 i, f, d;\n\t"             // sigmaA half1
        "mul.f32 h, e, a;\n\t"             // sigmaB half0 = uA0/den0
        "mul.f32 j, f, b;\n\t"             // sigmaB half1
        "mov.b64 s1, {g, i};\n\t"          // sigmaA pair
        "mov.b64 s2, {h, j};\n\t"          // sigmaB pair
        "fma.rn.f32x2 %0, s1, %4, %0;\n\t" // aP += sigmaA*pA
        "fma.rn.f32x2 %0, s2, %5, %0;\n\t" // aP += sigmaB*pB
        "add.rn.f32x2 %1, %1, s1;\n\t"     // aS += sigmaA
        "add.rn.f32x2 %1, %1, s2;\n\t"     // aS += sigmaB
        "}"
        : "+l"(aP), "+l"(aS)
        : "l"(zA), "l"(zB), "l"(pA2), "l"(pB2));
}

#define C_SCALE (-14.4269504088896341f)   // -10*log2(e): conv emits w; sigma = 1/(1+2^w)

// Setup: Winograd F(2,3) weight transform in the w-domain + constants.
__global__ void setup_kernel(const float* __restrict__ w,
                             const float* __restrict__ react,
                             const float* __restrict__ prod)
{
    int tid = threadIdx.x;            // 0..255 = NK*16
    int k = tid >> 4, j16 = tid & 15;
    u64 v = 0ull;
    if (j16 < 12) {
        int i = j16 / 3, jr = j16 - 3 * i;
        float g0 = C_SCALE * w[k * 9 + jr * 3 + 0];
        float g1 = C_SCALE * w[k * 9 + jr * 3 + 1];
        float g2 = C_SCALE * w[k * 9 + jr * 3 + 2];
        float u;
        if      (i == 0) u = g0;
        else if (i == 1) u = 0.5f * (g0 + g1 + g2);
        else if (i == 2) u = 0.5f * (g0 - g1 + g2);
        else             u = g2;
        v = pack2(u, u);
    } else if (j16 == 12) {
        float t = -C_SCALE * react[k];        // bias: w = C*N + (-C)*r
        v = pack2(t, t);
    } else if (j16 == 13) {
        float t = prod[k];
        v = pack2(t, t);
    }
    g_cb.crec[k][j16] = v;
}

// Winograd F(2,3) conv for one kernel: 16 packed fma-ops -> z pairs for 2 columns.
__device__ __forceinline__ void wino_conv(const u64* cr,
                                          const u64 P0[3], const u64 P1[3],
                                          const u64 P2[3], const u64 P3[3],
                                          u64& z0, u64& z1) {
    u64 m0 = mul2_(cr[0], P0[0]);
    u64 m1 = fma2(cr[3], P1[0], cr[12]);   // bias folded into m1
    u64 m2 = mul2_(cr[6], P2[0]);
    u64 m3 = mul2_(cr[9], P3[0]);
    m0 = fma2(cr[1],  P0[1], m0);  m1 = fma2(cr[4],  P1[1], m1);
    m2 = fma2(cr[7],  P2[1], m2);  m3 = fma2(cr[10], P3[1], m3);
    m0 = fma2(cr[2],  P0[2], m0);  m1 = fma2(cr[5],  P1[2], m1);
    m2 = fma2(cr[8],  P2[2], m2);  m3 = fma2(cr[11], P3[2], m3);
    z0 = add2_(m0, add2_(m1, m2));     // col gx
    z1 = sub2_(sub2_(m1, m2), m3);     // col gx+1
}

// Grid: (4 col-tiles, 64 row-tiles, 16 batch). Block (64,4) = 256 thr.
// Thread: 2 rows x 2 cols = 4 px, VERTICAL pairs per column.
__global__ void __launch_bounds__(256, 3)
ca_kernel(const float* __restrict__ x, float* __restrict__ out)
{
    __shared__ __align__(16) float tile[10][TW];

    const int bx  = blockIdx.x;
    const int by  = blockIdx.y;
    const int b   = blockIdx.z;
    const int tx  = threadIdx.x;
    const int ty  = threadIdx.y;
    const int tid = ty * 64 + tx;

    // ---- tile load: 10 rows x 34 float4 ----
    const float* xb = x + (size_t)b * (512 * 512);
    #pragma unroll
    for (int it = 0; it < 2; it++) {
        int i = tid + it * 256;
        if (i < 340) {
            int r   = i / 34;
            int c4  = i - r * 34;
            int gy  = by * 8 + r - 1;
            int gc0 = bx * 128 + c4 * 4 - 4;
            float4 v = make_float4(0.f, 0.f, 0.f, 0.f);
            if ((unsigned)gy < 512u && (unsigned)gc0 < 512u)
                v = *(const float4*)(xb + (size_t)gy * 512 + gc0);
            *(float4*)&tile[r][c4 * 4] = v;
        }
    }
    __syncthreads();

    // ---- 4x4 input patch (rows q=0..3, cols gx-1..gx+2) ----
    float d0[4], d1[4], d2[4], d3[4];
    #pragma unroll
    for (int q = 0; q < 4; q++) {
        const float* trow = tile[2 * ty + q];
        d0[q] = trow[2 * tx + 3];
        u64 M = *(const u64*)(trow + 2 * tx + 4);
        unpack2(M, d1[q], d2[q]);
        d3[q] = trow[2 * tx + 6];
    }
    const u64 xc0 = pack2(d1[1], d1[2]);   // x centers col gx,   rows (0,1)
    const u64 xc1 = pack2(d2[1], d2[2]);   // x centers col gx+1, rows (0,1)

    // ---- input Winograd transform over vertical (q,q+1) pairs ----
    u64 P0[3], P1[3], P2[3], P3[3];
    #pragma unroll
    for (int j = 0; j < 3; j++) {
        u64 V0 = pack2(d0[j], d0[j + 1]);
        u64 V1 = pack2(d1[j], d1[j + 1]);
        u64 V2 = pack2(d2[j], d2[j + 1]);
        u64 V3 = pack2(d3[j], d3[j + 1]);
        P0[j] = sub2_(V0, V2);
        P1[j] = add2_(V1, V2);
        P2[j] = sub2_(V2, V1);
        P3[j] = sub2_(V1, V3);
    }

    const u64 ONE2 = pack2(1.0f, 1.0f);

    u64 aP0 = 0ull, aP1 = 0ull;   // sum(sigma_k * p_k), cols 0/1
    u64 aS0 = 0ull, aS1 = 0ull;   // sum(sigma_k)

    // ---- 8 kernel-pairs: Winograd conv x2, then hand-authored paired tail ----
    #pragma unroll
    for (int j = 0; j < 8; j++) {
        const u64* crA = c_cb.crec[2 * j];
        const u64* crB = c_cb.crec[2 * j + 1];

        u64 zA0, zA1, zB0, zB1;
        wino_conv(crA, P0, P1, P2, P3, zA0, zA1);
        wino_conv(crB, P0, P1, P2, P3, zB0, zB1);

        const u64 pA = crA[13], pB = crB[13];
        pair_sig_acc(zA0, zB0, pA, pB, aP0, aS0);   // col gx
        pair_sig_acc(zA1, zB1, pA, pB, aP1, aS1);   // col gx+1
    }

    // ---- epilogue: out = sat( x*(1 - aS) + aP ) ----
    u64 o0 = fma2(xc0, sub2_(ONE2, aS0), aP0);
    u64 o1 = fma2(xc1, sub2_(ONE2, aS1), aP1);
    float a0, a1, b0, b1;
    unpack2(o0, a0, a1);    // a0 = row0 col0, a1 = row1 col0
    unpack2(o1, b0, b1);

    const int gy0 = by * 8 + 2 * ty;
    float* ob = out + (size_t)b * (512 * 512) + (size_t)gy0 * 512 + bx * 128 + 2 * tx;
    *(float2*)ob         = make_float2(sat_(a0), sat_(b0));
    *(float2*)(ob + 512) = make_float2(sat_(a1), sat_(b1));
}

extern "C" void kernel_launch(void* const* d_in, const int* in_sizes, int n_in,
                              void* d_out, int out_size) {
    const float* x = (const float*)d_in[0];
    const float* w = (const float*)d_in[1];
    const float* r = (const float*)d_in[2];
    const float* p = (const float*)d_in[3];

    setup_kernel<<<1, 256>>>(w, r, p);

    void* gsym = nullptr;
    cudaGetSymbolAddress(&gsym, g_cb);
    cudaMemcpyToSymbolAsync(c_cb, gsym, sizeof(CB), 0, cudaMemcpyDeviceToDevice, 0);

    dim3 grid(4, 64, 16);
    dim3 block(64, 4);
    ca_kernel<<<grid, block>>>(x, (float*)d_out);
}

// round 13
// speedup vs baseline: 1.4428x; 1.4428x over previous
#include <cuda_runtime.h>

typedef unsigned long long u64;

#define NK 16
#define TW 136           // tile row stride in floats (col c stores gcol = bx*128 + c - 4)

struct CB {
    u64 crec[NK][12];    // [w0..w8 (x5, dup), mk=(-5r,dup), pk=(0.5p,dup), pad]
    float psumh;         // 0.5 * sum(products)
    float pad;
};

__device__   CB g_cb;    // written by setup kernel
__constant__ CB c_cb;    // main kernel reads (uniform const port, off the smem crossbar)

__device__ __forceinline__ u64 pack2(float lo, float hi) {
    u64 r; asm("mov.b64 %0, {%1, %2};" : "=l"(r) : "f"(lo), "f"(hi)); return r;
}
__device__ __forceinline__ void unpack2(u64 v, float& lo, float& hi) {
    asm("mov.b64 {%0, %1}, %2;" : "=f"(lo), "=f"(hi) : "l"(v));
}
__device__ __forceinline__ u64 fma2(u64 a, u64 b, u64 c) {
    u64 d; asm("fma.rn.f32x2 %0, %1, %2, %3;" : "=l"(d) : "l"(a), "l"(b), "l"(c)); return d;
}
__device__ __forceinline__ u64 add2_(u64 a, u64 b) {
    u64 d; asm("add.rn.f32x2 %0, %1, %2;" : "=l"(d) : "l"(a), "l"(b)); return d;
}
__device__ __forceinline__ void tanh2_ip(u64& v) {
    asm("{\n\t"
        ".reg .f32 lo, hi;\n\t"
        "mov.b64 {lo, hi}, %0;\n\t"
        "tanh.approx.f32 lo, lo;\n\t"
        "tanh.approx.f32 hi, hi;\n\t"
        "mov.b64 %0, {lo, hi};\n\t"
        "}" : "+l"(v));
}
__device__ __forceinline__ float addsat_(float a, float b) {
    float r; asm("add.rn.sat.f32 %0, %1, %2;" : "=f"(r) : "f"(a), "f"(b)); return r;
}

// Setup: transform raw params into the packed constant record (1 block, 256 thr).
__global__ void setup_kernel(const float* __restrict__ w,
                             const float* __restrict__ react,
                             const float* __restrict__ prod)
{
    int tid = threadIdx.x;
    if (tid < NK * 12) {
        int k = tid / 12, j = tid - k * 12;
        u64 v = 0ull;
        if (j < 9) {
            float t = 5.0f * w[k * 9 + j];       // fold GAIN/2 into weights
            v = pack2(t, t);
        } else if (j == 9) {
            float t = -5.0f * react[k];          // z = 5N - 5r
            v = pack2(t, t);
        } else if (j == 10) {
            float t = 0.5f * prod[k];
            v = pack2(t, t);
        }
        g_cb.crec[k][j] = v;
    } else if (tid == NK * 12) {
        float s = 0.0f;
        #pragma unroll
        for (int k = 0; k < NK; k++) s += prod[k];
        g_cb.psumh = 0.5f * s;
        g_cb.pad = 0.0f;
    }
}

// Grid: (4 col-tiles, 64 row-tiles, 16 batch). Block (64,4) = 256 thr.
// Block covers 8 rows x 128 cols. Thread: 2 rows x 2 cols = 4 px (2 pairs).
__global__ void __launch_bounds__(256, 4)
ca_kernel(const float* __restrict__ x, float* __restrict__ out)
{
    __shared__ __align__(16) float tile[10][TW];   // rows gy0-1 .. gy0+8

    const int bx  = blockIdx.x;
    const int by  = blockIdx.y;
    const int b   = blockIdx.z;
    const int tx  = threadIdx.x;            // 0..63 -> col pair 2*tx
    const int ty  = threadIdx.y;            // 0..3  -> rows 2*ty, 2*ty+1
    const int tid = ty * 64 + tx;

    // ---- tile load: 10 rows x 34 float4 = 340 loads ----
    // tile[r][c] stores gcol = bx*128 + c - 4, row gy = by*8 + r - 1.
    const float* xb = x + (size_t)b * (512 * 512);
    #pragma unroll
    for (int it = 0; it < 2; it++) {
        int i = tid + it * 256;
        if (i < 340) {
            int r   = i / 34;
            int c4  = i - r * 34;
            int gy  = by * 8 + r - 1;
            int gc0 = bx * 128 + c4 * 4 - 4;
            float4 v = make_float4(0.f, 0.f, 0.f, 0.f);
            if ((unsigned)gy < 512u && (unsigned)gc0 < 512u)
                v = *(const float4*)(xb + (size_t)gy * 512 + gc0);
            *(float4*)&tile[r][c4 * 4] = v;
        }
    }
    __syncthreads();

    // ---- register neighborhood: 4 tile rows x 3 windows (all LDS.64-aligned) ----
    u64 nb[4][3];
    #pragma unroll
    for (int q = 0; q < 4; q++) {
        const float* trow = tile[2 * ty + q];
        u64 L = *(const u64*)(trow + 2 * tx + 2);
        u64 M = *(const u64*)(trow + 2 * tx + 4);
        u64 R = *(const u64*)(trow + 2 * tx + 6);
        float l0, l1, m0, m1, r0, r1;
        unpack2(L, l0, l1);
        unpack2(M, m0, m1);
        unpack2(R, r0, r1);
        nb[q][0] = pack2(l1, m0);   // (v0, v1)
        nb[q][1] = M;               // (v1, v2)
        nb[q][2] = pack2(m1, r0);   // (v2, v3)
    }

    u64 aP0 = 0ull, aP1 = 0ull;   // sum(t_k * 0.5 p_k), rows 0/1
    u64 aS0 = 0ull, aS1 = 0ull;   // sum(t_k)

    #pragma unroll
    for (int k = 0; k < NK; k++) {
        const u64* cr = c_cb.crec[k];    // uniform const loads (ULDC), no smem traffic
        const u64 mk  = cr[9];
        const u64 pkk = cr[10];

        // conv chains init with bias -> z = 5N - 5r directly
        u64 z0 = fma2(cr[0], nb[0][0], mk);     // row 0 (tile rows 0..2)
        u64 z1 = fma2(cr[0], nb[1][0], mk);     // row 1 (tile rows 1..3)
        z0 = fma2(cr[1], nb[0][1], z0);  z1 = fma2(cr[1], nb[1][1], z1);
        z0 = fma2(cr[2], nb[0][2], z0);  z1 = fma2(cr[2], nb[1][2], z1);
        z0 = fma2(cr[3], nb[1][0], z0);  z1 = fma2(cr[3], nb[2][0], z1);
        z0 = fma2(cr[4], nb[1][1], z0);  z1 = fma2(cr[4], nb[2][1], z1);
        z0 = fma2(cr[5], nb[1][2], z0);  z1 = fma2(cr[5], nb[2][2], z1);
        z0 = fma2(cr[6], nb[2][0], z0);  z1 = fma2(cr[6], nb[3][0], z1);
        z0 = fma2(cr[7], nb[2][1], z0);  z1 = fma2(cr[7], nb[3][1], z1);
        z0 = fma2(cr[8], nb[2][2], z0);  z1 = fma2(cr[8], nb[3][2], z1);

        tanh2_ip(z0);
        tanh2_ip(z1);

        aP0 = fma2(z0, pkk, aP0);  aS0 = add2_(z0, aS0);
        aP1 = fma2(z1, pkk, aP1);  aS1 = add2_(z1, aS1);
    }

    // ---- epilogue: out = sat( 0.5*sum(p) + aP + x*(-0.5*aS - 7) ) ----
    const float ps = c_cb.psumh;
    const u64 MH2 = pack2(-0.5f, -0.5f);
    const u64 M72 = pack2(-7.0f, -7.0f);

    u64 o0 = fma2(nb[1][1], fma2(aS0, MH2, M72), aP0);   // centers row 0
    u64 o1 = fma2(nb[2][1], fma2(aS1, MH2, M72), aP1);   // centers row 1
    float a0, a1, b0, b1;
    unpack2(o0, a0, a1);
    unpack2(o1, b0, b1);

    const int gy0 = by * 8 + 2 * ty;
    float* ob = out + (size_t)b * (512 * 512) + (size_t)gy0 * 512 + bx * 128 + 2 * tx;
    *(float2*)ob         = make_float2(addsat_(a0, ps), addsat_(a1, ps));
    *(float2*)(ob + 512) = make_float2(addsat_(b0, ps), addsat_(b1, ps));
}

extern "C" void kernel_launch(void* const* d_in, const int* in_sizes, int n_in,
                              void* d_out, int out_size) {
    const float* x = (const float*)d_in[0];
    const float* w = (const float*)d_in[1];
    const float* r = (const float*)d_in[2];
    const float* p = (const float*)d_in[3];

    // 1) compute transformed constants into g_cb (device global)
    setup_kernel<<<1, 256>>>(w, r, p);

    // 2) D2D async copy into __constant__ (graph-capturable memcpy node)
    void* gsym = nullptr;
    cudaGetSymbolAddress(&gsym, g_cb);
    cudaMemcpyToSymbolAsync(c_cb, gsym, sizeof(CB), 0, cudaMemcpyDeviceToDevice, 0);

    // 3) main kernel
    dim3 grid(4, 64, 16);   // 4 col-tiles x 64 row-tiles x 16 batch
    dim3 block(64, 4);
    ca_kernel<<<grid, block>>>(x, (float*)d_out);
}

// round 14
// speedup vs baseline: 1.4814x; 1.0267x over previous
#include <cuda_runtime.h>

typedef unsigned long long u64;

#define NK 16
#define TW 136           // tile row stride in floats (col c stores gcol = bx*128 + c - 4)

struct CB {
    u64 crec[NK][12];    // [w0..w8 (x5, dup), mk=(-5r,dup), pk=(0.5p,dup), pad]
    float psumh;         // 0.5 * sum(products)
    float pad;
};

__constant__ CB c_cb;    // main kernel reads via uniform const port; backing store
                         // written directly by setup_kernel (no memcpy node)

__device__ __forceinline__ u64 pack2(float lo, float hi) {
    u64 r; asm("mov.b64 %0, {%1, %2};" : "=l"(r) : "f"(lo), "f"(hi)); return r;
}
__device__ __forceinline__ void unpack2(u64 v, float& lo, float& hi) {
    asm("mov.b64 {%0, %1}, %2;" : "=f"(lo), "=f"(hi) : "l"(v));
}
__device__ __forceinline__ u64 fma2(u64 a, u64 b, u64 c) {
    u64 d; asm("fma.rn.f32x2 %0, %1, %2, %3;" : "=l"(d) : "l"(a), "l"(b), "l"(c)); return d;
}
__device__ __forceinline__ u64 add2_(u64 a, u64 b) {
    u64 d; asm("add.rn.f32x2 %0, %1, %2;" : "=l"(d) : "l"(a), "l"(b)); return d;
}
__device__ __forceinline__ void tanh2_ip(u64& v) {
    asm("{\n\t"
        ".reg .f32 lo, hi;\n\t"
        "mov.b64 {lo, hi}, %0;\n\t"
        "tanh.approx.f32 lo, lo;\n\t"
        "tanh.approx.f32 hi, hi;\n\t"
        "mov.b64 %0, {lo, hi};\n\t"
        "}" : "+l"(v));
}
__device__ __forceinline__ float addsat_(float a, float b) {
    float r; asm("add.rn.sat.f32 %0, %1, %2;" : "=f"(r) : "f"(a), "f"(b)); return r;
}

// Setup: transform raw params and write DIRECTLY into c_cb's backing store
// (global-space alias passed from host). 1 block, 256 threads.
__global__ void setup_kernel(CB* __restrict__ dst,
                             const float* __restrict__ w,
                             const float* __restrict__ react,
                             const float* __restrict__ prod)
{
    int tid = threadIdx.x;
    if (tid < NK * 12) {
        int k = tid / 12, j = tid - k * 12;
        u64 v = 0ull;
        if (j < 9) {
            float t = 5.0f * w[k * 9 + j];       // fold GAIN/2 into weights
            v = pack2(t, t);
        } else if (j == 9) {
            float t = -5.0f * react[k];          // z = 5N - 5r
            v = pack2(t, t);
        } else if (j == 10) {
            float t = 0.5f * prod[k];
            v = pack2(t, t);
        }
        dst->crec[k][j] = v;
    } else if (tid == NK * 12) {
        float s = 0.0f;
        #pragma unroll
        for (int k = 0; k < NK; k++) s += prod[k];
        dst->psumh = 0.5f * s;
        dst->pad = 0.0f;
    }
}

// Grid: (4 col-tiles, 64 row-tiles, 16 batch). Block (64,4) = 256 thr.
// Block covers 8 rows x 128 cols. Thread: 2 rows x 2 cols = 4 px (2 pairs).
__global__ void __launch_bounds__(256, 4)
ca_kernel(const float* __restrict__ x, float* __restrict__ out)
{
    __shared__ __align__(16) float tile[10][TW];   // rows gy0-1 .. gy0+8

    const int bx  = blockIdx.x;
    const int by  = blockIdx.y;
    const int b   = blockIdx.z;
    const int tx  = threadIdx.x;            // 0..63 -> col pair 2*tx
    const int ty  = threadIdx.y;            // 0..3  -> rows 2*ty, 2*ty+1
    const int tid = ty * 64 + tx;

    // ---- tile load: 10 rows x 34 float4 = 340 loads ----
    const float* xb = x + (size_t)b * (512 * 512);
    #pragma unroll
    for (int it = 0; it < 2; it++) {
        int i = tid + it * 256;
        if (i < 340) {
            int r   = i / 34;
            int c4  = i - r * 34;
            int gy  = by * 8 + r - 1;
            int gc0 = bx * 128 + c4 * 4 - 4;
            float4 v = make_float4(0.f, 0.f, 0.f, 0.f);
            if ((unsigned)gy < 512u && (unsigned)gc0 < 512u)
                v = *(const float4*)(xb + (size_t)gy * 512 + gc0);
            *(float4*)&tile[r][c4 * 4] = v;
        }
    }
    __syncthreads();

    // ---- register neighborhood: 4 tile rows x 3 windows (all LDS.64-aligned) ----
    u64 nb[4][3];
    #pragma unroll
    for (int q = 0; q < 4; q++) {
        const float* trow = tile[2 * ty + q];
        u64 L = *(const u64*)(trow + 2 * tx + 2);
        u64 M = *(const u64*)(trow + 2 * tx + 4);
        u64 R = *(const u64*)(trow + 2 * tx + 6);
        float l0, l1, m0, m1, r0, r1;
        unpack2(L, l0, l1);
        unpack2(M, m0, m1);
        unpack2(R, r0, r1);
        nb[q][0] = pack2(l1, m0);   // (v0, v1)
        nb[q][1] = M;               // (v1, v2)
        nb[q][2] = pack2(m1, r0);   // (v2, v3)
    }

    u64 aP0 = 0ull, aP1 = 0ull;   // sum(t_k * 0.5 p_k), rows 0/1
    u64 aS0 = 0ull, aS1 = 0ull;   // sum(t_k)

    #pragma unroll
    for (int k = 0; k < NK; k++) {
        const u64* cr = c_cb.crec[k];    // uniform const loads (ULDC), no smem traffic
        const u64 mk  = cr[9];
        const u64 pkk = cr[10];

        // conv chains init with bias -> z = 5N - 5r directly
        u64 z0 = fma2(cr[0], nb[0][0], mk);     // row 0 (tile rows 0..2)
        u64 z1 = fma2(cr[0], nb[1][0], mk);     // row 1 (tile rows 1..3)
        z0 = fma2(cr[1], nb[0][1], z0);  z1 = fma2(cr[1], nb[1][1], z1);
        z0 = fma2(cr[2], nb[0][2], z0);  z1 = fma2(cr[2], nb[1][2], z1);
        z0 = fma2(cr[3], nb[1][0], z0);  z1 = fma2(cr[3], nb[2][0], z1);
        z0 = fma2(cr[4], nb[1][1], z0);  z1 = fma2(cr[4], nb[2][1], z1);
        z0 = fma2(cr[5], nb[1][2], z0);  z1 = fma2(cr[5], nb[2][2], z1);
        z0 = fma2(cr[6], nb[2][0], z0);  z1 = fma2(cr[6], nb[3][0], z1);
        z0 = fma2(cr[7], nb[2][1], z0);  z1 = fma2(cr[7], nb[3][1], z1);
        z0 = fma2(cr[8], nb[2][2], z0);  z1 = fma2(cr[8], nb[3][2], z1);

        tanh2_ip(z0);
        tanh2_ip(z1);

        aP0 = fma2(z0, pkk, aP0);  aS0 = add2_(z0, aS0);
        aP1 = fma2(z1, pkk, aP1);  aS1 = add2_(z1, aS1);
    }

    // ---- epilogue: out = sat( 0.5*sum(p) + aP + x*(-0.5*aS - 7) ) ----
    const float ps = c_cb.psumh;
    const u64 MH2 = pack2(-0.5f, -0.5f);
    const u64 M72 = pack2(-7.0f, -7.0f);

    u64 o0 = fma2(nb[1][1], fma2(aS0, MH2, M72), aP0);   // centers row 0
    u64 o1 = fma2(nb[2][1], fma2(aS1, MH2, M72), aP1);   // centers row 1
    float a0, a1, b0, b1;
    unpack2(o0, a0, a1);
    unpack2(o1, b0, b1);

    const int gy0 = by * 8 + 2 * ty;
    float* ob = out + (size_t)b * (512 * 512) + (size_t)gy0 * 512 + bx * 128 + 2 * tx;
    *(float2*)ob         = make_float2(addsat_(a0, ps), addsat_(a1, ps));
    *(float2*)(ob + 512) = make_float2(addsat_(b0, ps), addsat_(b1, ps));
}

extern "C" void kernel_launch(void* const* d_in, const int* in_sizes, int n_in,
                              void* d_out, int out_size) {
    const float* x = (const float*)d_in[0];
    const float* w = (const float*)d_in[1];
    const float* r = (const float*)d_in[2];
    const float* p = (const float*)d_in[3];

    // Global-space alias of c_cb's backing store; setup_kernel writes it
    // directly, removing the memcpy node. Launch boundary fences the writes
    // and invalidates the const cache before ca_kernel reads.
    void* csym = nullptr;
    cudaGetSymbolAddress(&csym, c_cb);

    setup_kernel<<<1, 256>>>((CB*)csym, w, r, p);

    dim3 grid(4, 64, 16);   // 4 col-tiles x 64 row-tiles x 16 batch
    dim3 block(64, 4);
    ca_kernel<<<grid, block>>>(x, (float*)d_out);
}